// round 16
// baseline (speedup 1.0000x reference)
#include <cuda_runtime.h>
#include <cuda_bf16.h>
#include <math.h>
#include <stdint.h>

#define BB 256
#define TT 512
#define FF 256
#define HH 256
#define GG 1024
#define MM (TT * BB)
#define NT 512   /* threads per CTA */

// ---------------- device globals (no runtime allocation) --------------------
__device__ __nv_bfloat16 g_xhi[(size_t)MM * FF];    // 64 MB, row m = t*B+b
__device__ __nv_bfloat16 g_xlo[(size_t)MM * FF];
__device__ __nv_bfloat16 g_h1hi[(size_t)MM * HH];   // layer-1 h sequence
__device__ __nv_bfloat16 g_h1lo[(size_t)MM * HH];
__device__ __nv_bfloat16 g_h2hi[2 * BB * HH];       // layer-2 h ring
__device__ __nv_bfloat16 g_h2lo[2 * BB * HH];
__device__ float g_hlast[BB * HH];
__device__ unsigned g_flags[8 * 32];                 // [layer*4+grp]*32

// ---------------- helpers ----------------------------------------------------
__device__ __forceinline__ float sigf(float v) { return 1.0f / (1.0f + __expf(-v)); }

__device__ __forceinline__ uint32_t smem_u32(const void* p) {
    uint32_t a;
    asm("{ .reg .u64 t; cvta.to.shared.u64 t, %1; cvt.u32.u64 %0, t; }"
        : "=r"(a) : "l"(p));
    return a;
}
__device__ __forceinline__ void ldmA(uint32_t& a0, uint32_t& a1,
                                     uint32_t& a2, uint32_t& a3, uint32_t addr) {
    asm volatile("ldmatrix.sync.aligned.m8n8.x4.shared.b16 {%0,%1,%2,%3}, [%4];"
                 : "=r"(a0), "=r"(a1), "=r"(a2), "=r"(a3) : "r"(addr));
}
__device__ __forceinline__ void ldmB(uint32_t& b0, uint32_t& b1, uint32_t addr) {
    asm volatile("ldmatrix.sync.aligned.m8n8.x2.trans.shared.b16 {%0,%1}, [%2];"
                 : "=r"(b0), "=r"(b1) : "r"(addr));
}
__device__ __forceinline__ void mma_bf16(float* d, uint32_t a0, uint32_t a1,
                                         uint32_t a2, uint32_t a3,
                                         uint32_t b0, uint32_t b1) {
    asm volatile(
        "mma.sync.aligned.m16n8k16.row.col.f32.bf16.bf16.f32 "
        "{%0,%1,%2,%3}, {%4,%5,%6,%7}, {%8,%9}, {%0,%1,%2,%3};"
        : "+f"(d[0]), "+f"(d[1]), "+f"(d[2]), "+f"(d[3])
        : "r"(a0), "r"(a1), "r"(a2), "r"(a3), "r"(b0), "r"(b1));
}
__device__ __forceinline__ void split_bf16(float v, __nv_bfloat16& hi, __nv_bfloat16& lo) {
    hi = __float2bfloat16_rn(v);
    lo = __float2bfloat16_rn(v - __bfloat162float(hi));
}
__device__ __forceinline__ void pollFlag(unsigned* f, unsigned target) {
    unsigned g;
    do {
        asm volatile("ld.acquire.gpu.u32 %0, [%1];" : "=r"(g) : "l"(f) : "memory");
    } while (g < target);
}
__device__ __forceinline__ void addFlag(unsigned* f) {
    unsigned old;
    asm volatile("atom.add.release.gpu.u32 %0, [%1], 1;"
                 : "=r"(old) : "l"(f) : "memory");
}

__global__ void init_flags_kernel() {
    if (threadIdx.x < 8 * 32) g_flags[threadIdx.x] = 0;
}

// ---------------------------------------------------------------------------
// conv_x: x[B][T][F] fp32 -> xhi/xlo bf16 rows m = t*B+b.
// ---------------------------------------------------------------------------
__global__ void conv_x_kernel(const float* __restrict__ x,
                              __nv_bfloat16* __restrict__ xhi,
                              __nv_bfloat16* __restrict__ xlo)
{
    const int gid = blockIdx.x * 256 + threadIdx.x;
    const int m = gid >> 5;
    const int c = (gid & 31) * 8;
    const int b = m & (BB - 1);
    const int t = m >> 8;
    const float* src = x + ((size_t)b * TT + t) * FF + c;
    float4 v0 = *(const float4*)src;
    float4 v1 = *(const float4*)(src + 4);
    float vv[8] = {v0.x, v0.y, v0.z, v0.w, v1.x, v1.y, v1.z, v1.w};
    __nv_bfloat16 hi8[8], lo8[8];
#pragma unroll
    for (int j = 0; j < 8; j++) split_bf16(vv[j], hi8[j], lo8[j]);
    *(uint4*)(xhi + (size_t)m * FF + c) = *(uint4*)hi8;
    *(uint4*)(xlo + (size_t)m * FF + c) = *(uint4*)lo8;
}

// ---------------------------------------------------------------------------
// Fused 2-layer pipelined LSTM. 128 CTAs x 512 thr (16 warps).
// bid<64: layer 1 (4 grps x 16 CTAs); bid>=64: layer 2.
// CTA tile: 64 batch rows x (4 gates x 16 hc).
// Warp (msub, gq): m-subtile msub=w&3 (16 rows), gate gq=w>>2 (16 hc cols).
// R14 sync skeleton EXACTLY: tid0 polls both flags at step start ->
// __syncthreads -> reg-prefetch W operand -> stage h(t-1) -> U-MMA ->
// STS W regs -> W-MMA -> epilogue (gate-0 warps) -> sync -> arrive.
// bf16 hi/lo split (3 MMA terms, merged accumulator), fp32 accum.
// ---------------------------------------------------------------------------
#define SA_STR 528
#define S_AHI 0
#define S_ALO 33792
#define S_BWH 67584
#define S_BWL 100352
#define S_BUH 133120
#define S_BUL 165888
#define S_Z   198656
#define ZST   52
#define S_TOT (S_Z + 64 * ZST * 4)   /* 211968 */
#define BL_OFF 32768

// Merged-acc pass (per warp: 1 gate, n=16 -> j in {0,1}).
__device__ __forceinline__ void mma_pass(float acc[2][4],
                                         uint32_t aHi, uint32_t aLo,
                                         uint32_t bBase)
{
#pragma unroll
    for (int kc = 0; kc < 16; kc++) {
        uint32_t ah0, ah1, ah2, ah3, al0, al1, al2, al3;
        ldmA(ah0, ah1, ah2, ah3, aHi + kc * 32);
        ldmA(al0, al1, al2, al3, aLo + kc * 32);
#pragma unroll
        for (int j = 0; j < 2; j++) {
            const uint32_t b = bBase + j * 16 + kc * 512;
            uint32_t bh0, bh1, bl0, bl1;
            ldmB(bh0, bh1, b);
            ldmB(bl0, bl1, b + BL_OFF);
            mma_bf16(acc[j], ah0, ah1, ah2, ah3, bh0, bh1);
            mma_bf16(acc[j], ah0, ah1, ah2, ah3, bl0, bl1);
            mma_bf16(acc[j], al0, al1, al2, al3, bh0, bh1);
        }
    }
}

__global__ void __launch_bounds__(NT, 1)
fused_lstm_kernel(const __nv_bfloat16* __restrict__ xhi,
                  const __nv_bfloat16* __restrict__ xlo,
                  const float* __restrict__ W1, const float* __restrict__ U1,
                  const float* __restrict__ b1,
                  const float* __restrict__ W2, const float* __restrict__ U2,
                  const float* __restrict__ b2,
                  __nv_bfloat16* __restrict__ h1hi,
                  __nv_bfloat16* __restrict__ h1lo,
                  __nv_bfloat16* __restrict__ h2hi,
                  __nv_bfloat16* __restrict__ h2lo,
                  float* __restrict__ hlast)
{
    extern __shared__ char smem[];
    const uint32_t sb = smem_u32(smem);
    float* zs = (float*)(smem + S_Z);

    const int tid  = threadIdx.x;
    const int w    = tid >> 5;
    const int lane = tid & 31;
    const int layer = blockIdx.x >> 6;
    const int sub   = blockIdx.x & 63;
    const int grp   = sub >> 4;
    const int gm0   = grp * 64;
    const int hc0   = (sub & 15) * 16;
    const int msub  = w & 3;
    const int gq    = w >> 2;         // gate 0..3; gate-0 warps do epilogue
    const int isEpi = (gq == 0);

    const float* Wsrc = layer ? W2 : W1;
    const float* Usrc = layer ? U2 : U1;
    const float* bsrc = layer ? b2 : b1;
    unsigned* ownFlag = &g_flags[(layer * 4 + grp) * 32];
    unsigned* l1Flag  = &g_flags[grp * 32];

    // ---- one-time B fills: W and U slices, bf16 hi/lo, [gate][k][16 hc] ----
    for (int i = tid; i < 4 * 256 * 2; i += NT) {
        const int g = i >> 9;
        const int k = (i >> 1) & 255;
        const int half = i & 1;
        const int co = g * HH + hc0 + half * 8;
        const uint32_t so = (uint32_t)(g * 8192 + k * 32 + half * 16);
        {
            const float* src = Wsrc + (size_t)k * GG + co;
            __nv_bfloat16 h8[8], l8[8];
#pragma unroll
            for (int j = 0; j < 8; j++) split_bf16(src[j], h8[j], l8[j]);
            *(uint4*)(smem + S_BWH + so) = *(uint4*)h8;
            *(uint4*)(smem + S_BWL + so) = *(uint4*)l8;
        }
        {
            const float* src = Usrc + (size_t)k * GG + co;
            __nv_bfloat16 h8[8], l8[8];
#pragma unroll
            for (int j = 0; j < 8; j++) split_bf16(src[j], h8[j], l8[j]);
            *(uint4*)(smem + S_BUH + so) = *(uint4*)h8;
            *(uint4*)(smem + S_BUL + so) = *(uint4*)l8;
        }
    }

    // fragment-native ownership (epilogue = gate-0 warps)
    const int r0 = msub * 16 + (lane >> 2);
    const int c  = (lane & 3) * 2;
    float biaf[4][2][2];
    if (isEpi) {
#pragma unroll
        for (int g = 0; g < 4; g++)
#pragma unroll
            for (int j = 0; j < 2; j++) {
                const float2 bb = *(const float2*)(bsrc + g * HH + hc0 + j * 8 + c);
                biaf[g][j][0] = bb.x;
                biaf[g][j][1] = bb.y;
            }
    }
    float creg[8];
#pragma unroll
    for (int i = 0; i < 8; i++) creg[i] = 0.f;

    const uint32_t aBase = (uint32_t)((msub * 16 + (lane & 15)) * SA_STR
                                      + (lane >> 4) * 16);
    const uint32_t aHi = sb + S_AHI + aBase;
    const uint32_t aLo = sb + S_ALO + aBase;
    const uint32_t bW = sb + S_BWH + gq * 8192 + (lane & 15) * 32;
    const uint32_t bU = sb + S_BUH + gq * 8192 + (lane & 15) * 32;

    const __nv_bfloat16* wsrc_hi = layer ? h1hi : xhi;
    const __nv_bfloat16* wsrc_lo = layer ? h1lo : xlo;

    for (int t = 0; t < TT; t++) {
        const int doU = (t > 0);

        // ---- 1. merged polls (R14 discipline: tid0 + barrier) ----
        if (tid == 0) {
            if (layer) pollFlag(l1Flag, 16u * (unsigned)(t + 1));
            if (doU)   pollFlag(ownFlag, 16u * (unsigned)t);
        }
        __syncthreads();

        // ---- 2. reg-prefetch W-pass operand (x(t) / h1(t)) ----
        uint4 pregh[4], pregl[4];
        {
            const size_t rowb = (size_t)t * BB + gm0;
#pragma unroll
            for (int i = 0; i < 4; i++) {
                const int id = tid + i * NT;
                const int r  = id >> 5;
                const int cc = id & 31;
                pregh[i] = *((const uint4*)(wsrc_hi + (rowb + r) * 256) + cc);
                pregl[i] = *((const uint4*)(wsrc_lo + (rowb + r) * 256) + cc);
            }
        }

        float accW[2][4], accU[2][4];
#pragma unroll
        for (int j = 0; j < 2; j++)
#pragma unroll
            for (int q = 0; q < 4; q++) {
                accW[j][q] = 0.f;
                accU[j][q] = 0.f;
            }

        // ---- 3. stage h(t-1), U pass ----
        if (doU) {
            if (layer == 0) {
                const size_t rowb = (size_t)(t - 1) * BB + gm0;
#pragma unroll
                for (int i = 0; i < 4; i++) {
                    const int id = tid + i * NT;
                    const int r  = id >> 5;
                    const int cc = id & 31;
                    const uint4 vh = *((const uint4*)(h1hi + (rowb + r) * HH) + cc);
                    const uint4 vl = *((const uint4*)(h1lo + (rowb + r) * HH) + cc);
                    *(uint4*)(smem + S_AHI + r * SA_STR + cc * 16) = vh;
                    *(uint4*)(smem + S_ALO + r * SA_STR + cc * 16) = vl;
                }
            } else {
                const __nv_bfloat16* shi = h2hi + (size_t)((t - 1) & 1) * BB * HH;
                const __nv_bfloat16* slo = h2lo + (size_t)((t - 1) & 1) * BB * HH;
#pragma unroll
                for (int i = 0; i < 4; i++) {
                    const int id = tid + i * NT;
                    const int r  = id >> 5;
                    const int cc = id & 31;
                    const uint4 vh = *((const uint4*)(shi + (size_t)(gm0 + r) * HH) + cc);
                    const uint4 vl = *((const uint4*)(slo + (size_t)(gm0 + r) * HH) + cc);
                    *(uint4*)(smem + S_AHI + r * SA_STR + cc * 16) = vh;
                    *(uint4*)(smem + S_ALO + r * SA_STR + cc * 16) = vl;
                }
            }
            __syncthreads();
            mma_pass(accU, aHi, aLo, bU);
            __syncthreads();   // all U-MMA reads of A done before overwrite
        }

        // ---- 4. STS prefetched regs, W pass ----
#pragma unroll
        for (int i = 0; i < 4; i++) {
            const int id = tid + i * NT;
            const int r  = id >> 5;
            const int cc = id & 31;
            *(uint4*)(smem + S_AHI + r * SA_STR + cc * 16) = pregh[i];
            *(uint4*)(smem + S_ALO + r * SA_STR + cc * 16) = pregl[i];
        }
        __syncthreads();
        mma_pass(accW, aHi, aLo, bW);

        // ---- 5. epilogue ----
        float v[2][4];
#pragma unroll
        for (int j = 0; j < 2; j++)
#pragma unroll
            for (int q = 0; q < 4; q++)
                v[j][q] = accW[j][q] + accU[j][q];

        if (!isEpi) {
            // gates f(1), g(2), o(3) -> zs block (gq-1)*16
#pragma unroll
            for (int j = 0; j < 2; j++) {
                *(float2*)&zs[r0 * ZST + (gq - 1) * 16 + j * 8 + c] =
                    make_float2(v[j][0], v[j][1]);
                *(float2*)&zs[(r0 + 8) * ZST + (gq - 1) * 16 + j * 8 + c] =
                    make_float2(v[j][2], v[j][3]);
            }
        }
        asm volatile("bar.sync %0, 128;" :: "r"(1 + msub) : "memory");

        if (isEpi) {
            float zfv[2][2][2], zgv[2][2][2], zov[2][2][2];  // [j][rh][cp]
#pragma unroll
            for (int j = 0; j < 2; j++)
#pragma unroll
                for (int rh = 0; rh < 2; rh++) {
                    const int zr = (r0 + rh * 8) * ZST + j * 8 + c;
                    const float2 a = *(float2*)&zs[zr + 0];
                    const float2 b = *(float2*)&zs[zr + 16];
                    const float2 d = *(float2*)&zs[zr + 32];
                    zfv[j][rh][0] = a.x; zfv[j][rh][1] = a.y;
                    zgv[j][rh][0] = b.x; zgv[j][rh][1] = b.y;
                    zov[j][rh][0] = d.x; zov[j][rh][1] = d.y;
                }
            float hv[2][2][2];
#pragma unroll
            for (int rh = 0; rh < 2; rh++)
#pragma unroll
                for (int j = 0; j < 2; j++)
#pragma unroll
                    for (int cp = 0; cp < 2; cp++) {
                        const int q = rh * 2 + cp;
                        const float zi = v[j][q]        + biaf[0][j][cp];
                        const float zf = zfv[j][rh][cp] + biaf[1][j][cp];
                        const float zg = zgv[j][rh][cp] + biaf[2][j][cp];
                        const float zo = zov[j][rh][cp] + biaf[3][j][cp];
                        const float ig = sigf(zi), fg = sigf(zf);
                        const float gg = __tanhf(zg), og = sigf(zo);
                        const int ci = rh * 4 + j * 2 + cp;
                        const float cn = fg * creg[ci] + ig * gg;
                        creg[ci] = cn;
                        hv[rh][j][cp] = og * __tanhf(cn);
                    }

#pragma unroll
            for (int rh = 0; rh < 2; rh++) {
                const int row = gm0 + r0 + rh * 8;
#pragma unroll
                for (int j = 0; j < 2; j++) {
                    const int colb = hc0 + j * 8 + c;
                    __nv_bfloat16 h0h, h1h_, h0l, h1l_;
                    split_bf16(hv[rh][j][0], h0h, h0l);
                    split_bf16(hv[rh][j][1], h1h_, h1l_);
                    const uint32_t phi = (uint32_t)__bfloat16_as_ushort(h0h)
                                       | ((uint32_t)__bfloat16_as_ushort(h1h_) << 16);
                    const uint32_t plo = (uint32_t)__bfloat16_as_ushort(h0l)
                                       | ((uint32_t)__bfloat16_as_ushort(h1l_) << 16);
                    if (layer == 0) {
                        const size_t off = ((size_t)t * BB + row) * HH + colb;
                        *(uint32_t*)(h1hi + off) = phi;
                        *(uint32_t*)(h1lo + off) = plo;
                    } else {
                        const size_t off = (size_t)(t & 1) * BB * HH
                                         + (size_t)row * HH + colb;
                        *(uint32_t*)(h2hi + off) = phi;
                        *(uint32_t*)(h2lo + off) = plo;
                        if (t == TT - 1)
                            *(float2*)(hlast + (size_t)row * HH + colb) =
                                make_float2(hv[rh][j][0], hv[rh][j][1]);
                    }
                }
            }
        }

        __syncthreads();
        if (tid == 0) addFlag(ownFlag);
    }
}

// ---------------------------------------------------------------------------
// out[b] = sum_k hlast[b][k] * Wd[k] + bd[0]
// ---------------------------------------------------------------------------
__global__ void dense_out_kernel(const float* __restrict__ hlast,
                                 const float* __restrict__ Wd,
                                 const float* __restrict__ bd,
                                 float* __restrict__ out)
{
    __shared__ float red[256];
    const int b = blockIdx.x;
    const int k = threadIdx.x;
    red[k] = hlast[b * HH + k] * Wd[k];
    __syncthreads();
    for (int s = 128; s > 0; s >>= 1) {
        if (k < s) red[k] += red[k + s];
        __syncthreads();
    }
    if (k == 0) out[b] = red[0] + bd[0];
}

// ---------------------------------------------------------------------------
// Launch: 4 graph nodes.
// ---------------------------------------------------------------------------
extern "C" void kernel_launch(void* const* d_in, const int* in_sizes, int n_in,
                              void* d_out, int out_size)
{
    const float* x  = (const float*)d_in[0];
    const float* W1 = (const float*)d_in[1];
    const float* U1 = (const float*)d_in[2];
    const float* b1 = (const float*)d_in[3];
    const float* W2 = (const float*)d_in[4];
    const float* U2 = (const float*)d_in[5];
    const float* b2 = (const float*)d_in[6];
    const float* Wd = (const float*)d_in[7];
    const float* bd = (const float*)d_in[8];
    float* out = (float*)d_out;

    float* hlast;
    __nv_bfloat16 *xhi, *xlo, *h1hi, *h1lo, *h2hi, *h2lo;
    cudaGetSymbolAddress((void**)&xhi, g_xhi);
    cudaGetSymbolAddress((void**)&xlo, g_xlo);
    cudaGetSymbolAddress((void**)&h1hi, g_h1hi);
    cudaGetSymbolAddress((void**)&h1lo, g_h1lo);
    cudaGetSymbolAddress((void**)&h2hi, g_h2hi);
    cudaGetSymbolAddress((void**)&h2lo, g_h2lo);
    cudaGetSymbolAddress((void**)&hlast, g_hlast);

    cudaFuncSetAttribute(fused_lstm_kernel,
                         cudaFuncAttributeMaxDynamicSharedMemorySize, S_TOT);

    conv_x_kernel<<<MM * 32 / 256, 256>>>(x, xhi, xlo);
    init_flags_kernel<<<1, 256>>>();
    fused_lstm_kernel<<<128, NT, S_TOT>>>(xhi, xlo, W1, U1, b1, W2, U2, b2,
                                          h1hi, h1lo, h2hi, h2lo, hlast);
    dense_out_kernel<<<BB, 256>>>(hlast, Wd, bd, out);
}

// round 17
// speedup vs baseline: 1.0462x; 1.0462x over previous
#include <cuda_runtime.h>
#include <cuda_bf16.h>
#include <math.h>
#include <stdint.h>

#define BB 256
#define TT 512
#define FF 256
#define HH 256
#define GG 1024
#define MM (TT * BB)

// ---------------- device globals (no runtime allocation) --------------------
__device__ __nv_bfloat16 g_xhi[(size_t)MM * FF];    // 64 MB, row m = t*B+b
__device__ __nv_bfloat16 g_xlo[(size_t)MM * FF];
__device__ __nv_bfloat16 g_h1hi[(size_t)MM * HH];   // layer-1 h sequence
__device__ __nv_bfloat16 g_h1lo[(size_t)MM * HH];
__device__ __nv_bfloat16 g_h2hi[2 * BB * HH];       // layer-2 h ring
__device__ __nv_bfloat16 g_h2lo[2 * BB * HH];
__device__ float g_hlast[BB * HH];
__device__ unsigned g_flags[8 * 32];                 // [layer*4+grp]*32

// ---------------- helpers ----------------------------------------------------
__device__ __forceinline__ float sigf(float v) { return 1.0f / (1.0f + __expf(-v)); }

__device__ __forceinline__ uint32_t smem_u32(const void* p) {
    uint32_t a;
    asm("{ .reg .u64 t; cvta.to.shared.u64 t, %1; cvt.u32.u64 %0, t; }"
        : "=r"(a) : "l"(p));
    return a;
}
__device__ __forceinline__ void ldmA(uint32_t& a0, uint32_t& a1,
                                     uint32_t& a2, uint32_t& a3, uint32_t addr) {
    asm volatile("ldmatrix.sync.aligned.m8n8.x4.shared.b16 {%0,%1,%2,%3}, [%4];"
                 : "=r"(a0), "=r"(a1), "=r"(a2), "=r"(a3) : "r"(addr));
}
__device__ __forceinline__ void ldmB(uint32_t& b0, uint32_t& b1, uint32_t addr) {
    asm volatile("ldmatrix.sync.aligned.m8n8.x2.trans.shared.b16 {%0,%1}, [%2];"
                 : "=r"(b0), "=r"(b1) : "r"(addr));
}
__device__ __forceinline__ void mma_bf16(float* d, uint32_t a0, uint32_t a1,
                                         uint32_t a2, uint32_t a3,
                                         uint32_t b0, uint32_t b1) {
    asm volatile(
        "mma.sync.aligned.m16n8k16.row.col.f32.bf16.bf16.f32 "
        "{%0,%1,%2,%3}, {%4,%5,%6,%7}, {%8,%9}, {%0,%1,%2,%3};"
        : "+f"(d[0]), "+f"(d[1]), "+f"(d[2]), "+f"(d[3])
        : "r"(a0), "r"(a1), "r"(a2), "r"(a3), "r"(b0), "r"(b1));
}
__device__ __forceinline__ void split_bf16(float v, __nv_bfloat16& hi, __nv_bfloat16& lo) {
    hi = __float2bfloat16_rn(v);
    lo = __float2bfloat16_rn(v - __bfloat162float(hi));
}
__device__ __forceinline__ void pollFlag(unsigned* f, unsigned target) {
    unsigned g;
    do {
        asm volatile("ld.acquire.gpu.u32 %0, [%1];" : "=r"(g) : "l"(f) : "memory");
    } while (g < target);
}
__device__ __forceinline__ void addFlag(unsigned* f) {
    unsigned old;
    asm volatile("atom.add.release.gpu.u32 %0, [%1], 1;"
                 : "=r"(old) : "l"(f) : "memory");
}

__global__ void init_flags_kernel() {
    if (threadIdx.x < 8 * 32) g_flags[threadIdx.x] = 0;
}

// ---------------------------------------------------------------------------
// conv_x: x[B][T][F] fp32 -> xhi/xlo bf16 rows m = t*B+b.
// ---------------------------------------------------------------------------
__global__ void conv_x_kernel(const float* __restrict__ x,
                              __nv_bfloat16* __restrict__ xhi,
                              __nv_bfloat16* __restrict__ xlo)
{
    const int gid = blockIdx.x * 256 + threadIdx.x;
    const int m = gid >> 5;
    const int c = (gid & 31) * 8;
    const int b = m & (BB - 1);
    const int t = m >> 8;
    const float* src = x + ((size_t)b * TT + t) * FF + c;
    float4 v0 = *(const float4*)src;
    float4 v1 = *(const float4*)(src + 4);
    float vv[8] = {v0.x, v0.y, v0.z, v0.w, v1.x, v1.y, v1.z, v1.w};
    __nv_bfloat16 hi8[8], lo8[8];
#pragma unroll
    for (int j = 0; j < 8; j++) split_bf16(vv[j], hi8[j], lo8[j]);
    *(uint4*)(xhi + (size_t)m * FF + c) = *(uint4*)hi8;
    *(uint4*)(xlo + (size_t)m * FF + c) = *(uint4*)lo8;
}

// ---------------------------------------------------------------------------
// Fused 2-layer pipelined LSTM. 128 CTAs x 256 thr.
// bid<64: layer 1 (4 grps x 16 CTAs); bid>=64: layer 2.
// CTA tile: 64 batch rows x (4 gates x 16 hc). Per step (R14 skeleton):
//   poll flags -> stage h(t-1) (LDGs issued FIRST) -> reg-prefetch W operand
//   -> sync -> U-MMA -> sync -> STS W regs -> sync -> W-MMA -> epilogue.
// bf16 hi/lo split (3 MMA terms, merged accumulator), fp32 accum.
// smem = 207872 B (identical to R14 layout).
// ---------------------------------------------------------------------------
#define SA_STR 528
#define S_AHI 0
#define S_ALO 33792
#define S_BWH 67584
#define S_BWL 100352
#define S_BUH 133120
#define S_BUL 165888
#define S_Z   198656
#define ZST   36
#define S_TOT (S_Z + 64 * ZST * 4)
#define BL_OFF 32768

// Merged-acc pass: 3 split terms into one acc set.
__device__ __forceinline__ void mma_pass(float acc[2][2][4],
                                         uint32_t aHi, uint32_t aLo,
                                         uint32_t bBase)
{
#pragma unroll
    for (int kc = 0; kc < 16; kc++) {
        uint32_t ah0, ah1, ah2, ah3, al0, al1, al2, al3;
        ldmA(ah0, ah1, ah2, ah3, aHi + kc * 32);
        ldmA(al0, al1, al2, al3, aLo + kc * 32);
#pragma unroll
        for (int gl = 0; gl < 2; gl++) {
#pragma unroll
            for (int j = 0; j < 2; j++) {
                const uint32_t b = bBase + gl * 8192 + j * 16 + kc * 512;
                uint32_t bh0, bh1, bl0, bl1;
                ldmB(bh0, bh1, b);
                ldmB(bl0, bl1, b + BL_OFF);
                mma_bf16(acc[gl][j], ah0, ah1, ah2, ah3, bh0, bh1);
                mma_bf16(acc[gl][j], ah0, ah1, ah2, ah3, bl0, bl1);
                mma_bf16(acc[gl][j], al0, al1, al2, al3, bh0, bh1);
            }
        }
    }
}

__global__ void __launch_bounds__(256, 1)
fused_lstm_kernel(const __nv_bfloat16* __restrict__ xhi,
                  const __nv_bfloat16* __restrict__ xlo,
                  const float* __restrict__ W1, const float* __restrict__ U1,
                  const float* __restrict__ b1,
                  const float* __restrict__ W2, const float* __restrict__ U2,
                  const float* __restrict__ b2,
                  __nv_bfloat16* __restrict__ h1hi,
                  __nv_bfloat16* __restrict__ h1lo,
                  __nv_bfloat16* __restrict__ h2hi,
                  __nv_bfloat16* __restrict__ h2lo,
                  float* __restrict__ hlast)
{
    extern __shared__ char smem[];
    const uint32_t sb = smem_u32(smem);
    float* zs = (float*)(smem + S_Z);

    const int tid  = threadIdx.x;
    const int w    = tid >> 5;
    const int lane = tid & 31;
    const int layer = blockIdx.x >> 6;
    const int sub   = blockIdx.x & 63;
    const int grp   = sub >> 4;
    const int gm0   = grp * 64;
    const int hc0   = (sub & 15) * 16;
    const int msub  = w & 3;
    const int gp    = w >> 2;         // 0: gates i,f (epilogue); 1: gates g,o
    const int isEpi = (gp == 0);

    const float* Wsrc = layer ? W2 : W1;
    const float* Usrc = layer ? U2 : U1;
    const float* bsrc = layer ? b2 : b1;
    unsigned* ownFlag = &g_flags[(layer * 4 + grp) * 32];
    unsigned* l1Flag  = &g_flags[grp * 32];

    // ---- one-time B fills: W and U slices, bf16 hi/lo, [gate][k][16 hc] ----
    for (int i = tid; i < 4 * 256 * 2; i += 256) {
        const int g = i >> 9;
        const int k = (i >> 1) & 255;
        const int half = i & 1;
        const int co = g * HH + hc0 + half * 8;
        const uint32_t so = (uint32_t)(g * 8192 + k * 32 + half * 16);
        {
            const float* src = Wsrc + (size_t)k * GG + co;
            __nv_bfloat16 h8[8], l8[8];
#pragma unroll
            for (int j = 0; j < 8; j++) split_bf16(src[j], h8[j], l8[j]);
            *(uint4*)(smem + S_BWH + so) = *(uint4*)h8;
            *(uint4*)(smem + S_BWL + so) = *(uint4*)l8;
        }
        {
            const float* src = Usrc + (size_t)k * GG + co;
            __nv_bfloat16 h8[8], l8[8];
#pragma unroll
            for (int j = 0; j < 8; j++) split_bf16(src[j], h8[j], l8[j]);
            *(uint4*)(smem + S_BUH + so) = *(uint4*)h8;
            *(uint4*)(smem + S_BUL + so) = *(uint4*)l8;
        }
    }

    // fragment-native ownership (epilogue warps)
    const int r0 = msub * 16 + (lane >> 2);
    const int c  = (lane & 3) * 2;
    float biaf[4][2][2];
    if (isEpi) {
#pragma unroll
        for (int g = 0; g < 4; g++)
#pragma unroll
            for (int j = 0; j < 2; j++) {
                const float2 bb = *(const float2*)(bsrc + g * HH + hc0 + j * 8 + c);
                biaf[g][j][0] = bb.x;
                biaf[g][j][1] = bb.y;
            }
    }
    float creg[8];
#pragma unroll
    for (int i = 0; i < 8; i++) creg[i] = 0.f;

    const uint32_t aBase = (uint32_t)((msub * 16 + (lane & 15)) * SA_STR
                                      + (lane >> 4) * 16);
    const uint32_t aHi = sb + S_AHI + aBase;
    const uint32_t aLo = sb + S_ALO + aBase;
    const uint32_t bW = sb + S_BWH + gp * 2 * 8192 + (lane & 15) * 32;
    const uint32_t bU = sb + S_BUH + gp * 2 * 8192 + (lane & 15) * 32;

    const __nv_bfloat16* wsrc_hi = layer ? h1hi : xhi;
    const __nv_bfloat16* wsrc_lo = layer ? h1lo : xlo;

    for (int t = 0; t < TT; t++) {
        const int doU = (t > 0);

        // ---- 1. merged polls (R14 discipline) ----
        if (tid == 0) {
            if (layer) pollFlag(l1Flag, 16u * (unsigned)(t + 1));
            if (doU)   pollFlag(ownFlag, 16u * (unsigned)t);
        }
        __syncthreads();

        // ---- 2. stage h(t-1) FIRST (critical-path LDGs at LSU queue head) ----
        if (doU) {
            if (layer == 0) {
                const size_t rowb = (size_t)(t - 1) * BB + gm0;
#pragma unroll
                for (int i = 0; i < 8; i++) {
                    const int id = tid + i * 256;
                    const int r  = id >> 5;
                    const int cc = id & 31;
                    const uint4 vh = *((const uint4*)(h1hi + (rowb + r) * HH) + cc);
                    const uint4 vl = *((const uint4*)(h1lo + (rowb + r) * HH) + cc);
                    *(uint4*)(smem + S_AHI + r * SA_STR + cc * 16) = vh;
                    *(uint4*)(smem + S_ALO + r * SA_STR + cc * 16) = vl;
                }
            } else {
                const __nv_bfloat16* shi = h2hi + (size_t)((t - 1) & 1) * BB * HH;
                const __nv_bfloat16* slo = h2lo + (size_t)((t - 1) & 1) * BB * HH;
#pragma unroll
                for (int i = 0; i < 8; i++) {
                    const int id = tid + i * 256;
                    const int r  = id >> 5;
                    const int cc = id & 31;
                    const uint4 vh = *((const uint4*)(shi + (size_t)(gm0 + r) * HH) + cc);
                    const uint4 vl = *((const uint4*)(slo + (size_t)(gm0 + r) * HH) + cc);
                    *(uint4*)(smem + S_AHI + r * SA_STR + cc * 16) = vh;
                    *(uint4*)(smem + S_ALO + r * SA_STR + cc * 16) = vl;
                }
            }
        }

        // ---- 3. reg-prefetch W-pass operand (x(t) / h1(t)): retires in the
        //         shadow of the U pass ----
        uint4 pregh[8], pregl[8];
        {
            const size_t rowb = (size_t)t * BB + gm0;
#pragma unroll
            for (int i = 0; i < 8; i++) {
                const int id = tid + i * 256;
                const int r  = id >> 5;
                const int cc = id & 31;
                pregh[i] = *((const uint4*)(wsrc_hi + (rowb + r) * 256) + cc);
                pregl[i] = *((const uint4*)(wsrc_lo + (rowb + r) * 256) + cc);
            }
        }

        float accW[2][2][4], accU[2][2][4];
#pragma unroll
        for (int gl = 0; gl < 2; gl++)
#pragma unroll
            for (int j = 0; j < 2; j++)
#pragma unroll
                for (int q = 0; q < 4; q++) {
                    accW[gl][j][q] = 0.f;
                    accU[gl][j][q] = 0.f;
                }

        // ---- 4. U pass ----
        if (doU) {
            __syncthreads();
            mma_pass(accU, aHi, aLo, bU);
            __syncthreads();   // all U-MMA reads of A done before overwrite
        }

        // ---- 5. STS prefetched regs, W pass ----
#pragma unroll
        for (int i = 0; i < 8; i++) {
            const int id = tid + i * 256;
            const int r  = id >> 5;
            const int cc = id & 31;
            *(uint4*)(smem + S_AHI + r * SA_STR + cc * 16) = pregh[i];
            *(uint4*)(smem + S_ALO + r * SA_STR + cc * 16) = pregl[i];
        }
        __syncthreads();
        mma_pass(accW, aHi, aLo, bW);

        // ---- 6. epilogue ----
        float v[2][2][4];
#pragma unroll
        for (int gl = 0; gl < 2; gl++)
#pragma unroll
            for (int j = 0; j < 2; j++)
#pragma unroll
                for (int q = 0; q < 4; q++)
                    v[gl][j][q] = accW[gl][j][q] + accU[gl][j][q];

        if (!isEpi) {
#pragma unroll
            for (int gl = 0; gl < 2; gl++)
#pragma unroll
                for (int j = 0; j < 2; j++) {
                    *(float2*)&zs[r0 * ZST + gl * 16 + j * 8 + c] =
                        make_float2(v[gl][j][0], v[gl][j][1]);
                    *(float2*)&zs[(r0 + 8) * ZST + gl * 16 + j * 8 + c] =
                        make_float2(v[gl][j][2], v[gl][j][3]);
                }
        }
        asm volatile("bar.sync %0, 64;" :: "r"(1 + msub) : "memory");

        if (isEpi) {
            float zgv[2][2][2], zov[2][2][2];
#pragma unroll
            for (int j = 0; j < 2; j++)
#pragma unroll
                for (int rh = 0; rh < 2; rh++) {
                    const float2 a = *(float2*)&zs[(r0 + rh * 8) * ZST + 0 + j * 8 + c];
                    const float2 b = *(float2*)&zs[(r0 + rh * 8) * ZST + 16 + j * 8 + c];
                    zgv[j][rh][0] = a.x; zgv[j][rh][1] = a.y;
                    zov[j][rh][0] = b.x; zov[j][rh][1] = b.y;
                }
            float hv[2][2][2];
#pragma unroll
            for (int rh = 0; rh < 2; rh++)
#pragma unroll
                for (int j = 0; j < 2; j++)
#pragma unroll
                    for (int cp = 0; cp < 2; cp++) {
                        const int q = rh * 2 + cp;
                        const float zi = v[0][j][q]     + biaf[0][j][cp];
                        const float zf = v[1][j][q]     + biaf[1][j][cp];
                        const float zg = zgv[j][rh][cp] + biaf[2][j][cp];
                        const float zo = zov[j][rh][cp] + biaf[3][j][cp];
                        const float ig = sigf(zi), fg = sigf(zf);
                        const float gg = __tanhf(zg), og = sigf(zo);
                        const int ci = rh * 4 + j * 2 + cp;
                        const float cn = fg * creg[ci] + ig * gg;
                        creg[ci] = cn;
                        hv[rh][j][cp] = og * __tanhf(cn);
                    }

#pragma unroll
            for (int rh = 0; rh < 2; rh++) {
                const int row = gm0 + r0 + rh * 8;
#pragma unroll
                for (int j = 0; j < 2; j++) {
                    const int colb = hc0 + j * 8 + c;
                    __nv_bfloat16 h0h, h1h_, h0l, h1l_;
                    split_bf16(hv[rh][j][0], h0h, h0l);
                    split_bf16(hv[rh][j][1], h1h_, h1l_);
                    const uint32_t phi = (uint32_t)__bfloat16_as_ushort(h0h)
                                       | ((uint32_t)__bfloat16_as_ushort(h1h_) << 16);
                    const uint32_t plo = (uint32_t)__bfloat16_as_ushort(h0l)
                                       | ((uint32_t)__bfloat16_as_ushort(h1l_) << 16);
                    if (layer == 0) {
                        const size_t off = ((size_t)t * BB + row) * HH + colb;
                        *(uint32_t*)(h1hi + off) = phi;
                        *(uint32_t*)(h1lo + off) = plo;
                    } else {
                        const size_t off = (size_t)(t & 1) * BB * HH
                                         + (size_t)row * HH + colb;
                        *(uint32_t*)(h2hi + off) = phi;
                        *(uint32_t*)(h2lo + off) = plo;
                        if (t == TT - 1)
                            *(float2*)(hlast + (size_t)row * HH + colb) =
                                make_float2(hv[rh][j][0], hv[rh][j][1]);
                    }
                }
            }
        }

        __syncthreads();
        if (tid == 0) addFlag(ownFlag);
    }
}

// ---------------------------------------------------------------------------
// out[b] = sum_k hlast[b][k] * Wd[k] + bd[0]
// ---------------------------------------------------------------------------
__global__ void dense_out_kernel(const float* __restrict__ hlast,
                                 const float* __restrict__ Wd,
                                 const float* __restrict__ bd,
                                 float* __restrict__ out)
{
    __shared__ float red[256];
    const int b = blockIdx.x;
    const int k = threadIdx.x;
    red[k] = hlast[b * HH + k] * Wd[k];
    __syncthreads();
    for (int s = 128; s > 0; s >>= 1) {
        if (k < s) red[k] += red[k + s];
        __syncthreads();
    }
    if (k == 0) out[b] = red[0] + bd[0];
}

// ---------------------------------------------------------------------------
// Launch: 4 graph nodes.
// ---------------------------------------------------------------------------
extern "C" void kernel_launch(void* const* d_in, const int* in_sizes, int n_in,
                              void* d_out, int out_size)
{
    const float* x  = (const float*)d_in[0];
    const float* W1 = (const float*)d_in[1];
    const float* U1 = (const float*)d_in[2];
    const float* b1 = (const float*)d_in[3];
    const float* W2 = (const float*)d_in[4];
    const float* U2 = (const float*)d_in[5];
    const float* b2 = (const float*)d_in[6];
    const float* Wd = (const float*)d_in[7];
    const float* bd = (const float*)d_in[8];
    float* out = (float*)d_out;

    float* hlast;
    __nv_bfloat16 *xhi, *xlo, *h1hi, *h1lo, *h2hi, *h2lo;
    cudaGetSymbolAddress((void**)&xhi, g_xhi);
    cudaGetSymbolAddress((void**)&xlo, g_xlo);
    cudaGetSymbolAddress((void**)&h1hi, g_h1hi);
    cudaGetSymbolAddress((void**)&h1lo, g_h1lo);
    cudaGetSymbolAddress((void**)&h2hi, g_h2hi);
    cudaGetSymbolAddress((void**)&h2lo, g_h2lo);
    cudaGetSymbolAddress((void**)&hlast, g_hlast);

    cudaFuncSetAttribute(fused_lstm_kernel,
                         cudaFuncAttributeMaxDynamicSharedMemorySize, S_TOT);

    conv_x_kernel<<<MM * 32 / 256, 256>>>(x, xhi, xlo);
    init_flags_kernel<<<1, 256>>>();
    fused_lstm_kernel<<<128, 256, S_TOT>>>(xhi, xlo, W1, U1, b1, W2, U2, b2,
                                           h1hi, h1lo, h2hi, h2lo, hlast);
    dense_out_kernel<<<BB, 256>>>(hlast, Wd, bd, out);
}